// round 12
// baseline (speedup 1.0000x reference)
#include <cuda_runtime.h>
#include <cuda_bf16.h>
#include <math.h>
#include <stdint.h>

// Problem constants
#define T0 512
#define TT 2048
#define WIDTH 2048
#define NH 16
#define KH 4
#define HD 128
#define KC_BASE (TT*WIDTH)
#define VC_BASE (KC_BASE + TT*KH*HD)
#define NEGV -2.3819763e38f

// Scratch
__device__ float g_qg[TT * NH * 256];
__device__ float g_kraw[TT * KH * HD];
__device__ float g_q[TT * NH * HD];     // tf32-rounded q
__device__ float g_ktf[TT * KH * HD];   // tf32-rounded roped K
__device__ float g_vtf[TT * KH * HD];   // tf32-rounded V
__device__ float g_enc[TT * NH * HD];   // tf32-rounded gated attention out

// tf32 pre-rounded GEMM operands
__device__ float g_xtf[TT * WIDTH];              // x0 | x1
__device__ float g_qgwtf[2 * NH * WIDTH * 256];  // qg_w0 | qg_w1
__device__ float g_kwtf[2 * KH * WIDTH * HD];    // k_w0 | k_w1
__device__ float g_vwtf[2 * KH * WIDTH * HD];    // v_w0 | v_w1
__device__ float g_owtf[2 * NH * HD * WIDTH];    // o_w0 | o_w1

// ---------------------------------------------------------------------------
// helpers
// ---------------------------------------------------------------------------
__device__ __forceinline__ uint32_t f2tf(float f) {
    uint32_t r;
    asm("cvt.rna.tf32.f32 %0, %1;" : "=r"(r) : "f"(f));
    return r;
}

__device__ __forceinline__ uint32_t smem_u32(const void* p) {
    uint32_t a;
    asm("{ .reg .u64 t; cvta.to.shared.u64 t, %1; cvt.u32.u64 %0, t; }"
        : "=r"(a) : "l"(p));
    return a;
}

__device__ __forceinline__ void cpasync16(uint32_t s, const float* g) {
    asm volatile("cp.async.ca.shared.global [%0], [%1], 16;" :: "r"(s), "l"(g));
}
__device__ __forceinline__ void cpasync16cg(uint32_t s, const float* g) {
    asm volatile("cp.async.cg.shared.global [%0], [%1], 16;" :: "r"(s), "l"(g));
}

// m16n8k8 tf32 MMA, fp32 accumulate.
__device__ __forceinline__ void mma8(float* c, const uint32_t* a, const uint32_t* b) {
    asm volatile(
        "mma.sync.aligned.m16n8k8.row.col.f32.tf32.tf32.f32 "
        "{%0,%1,%2,%3},{%4,%5,%6,%7},{%8,%9},{%0,%1,%2,%3};"
        : "+f"(c[0]), "+f"(c[1]), "+f"(c[2]), "+f"(c[3])
        : "r"(a[0]), "r"(a[1]), "r"(a[2]), "r"(a[3]), "r"(b[0]), "r"(b[1]));
}

// FMA-pipe exp (exp2 poly, |rel err| ~4e-5 << tf32 quantization).
__device__ __forceinline__ float exp_poly(float x) {
    float xl = x * 1.4426950408889634f;
    xl = fmaxf(fminf(xl, 125.0f), -125.0f);
    float nf = rintf(xl);
    float fr = xl - nf;
    float t = fmaf(0.0096183425f, fr, 0.055503327f);
    t = fmaf(t, fr, 0.24022651f);
    t = fmaf(t, fr, 0.69314718f);
    t = fmaf(t, fr, 1.0f);
    return __uint_as_float(__float_as_uint(t) + (int)nf * 8388608);
}

// ---------------------------------------------------------------------------
// Pre-round all GEMM operands to tf32 (grid.y = segment id).
// ---------------------------------------------------------------------------
__global__ __launch_bounds__(256) void preround_kernel(
    const float* __restrict__ x0, const float* __restrict__ x1,
    const float* __restrict__ qgw0, const float* __restrict__ qgw1,
    const float* __restrict__ kw0, const float* __restrict__ kw1,
    const float* __restrict__ vw0, const float* __restrict__ vw1,
    const float* __restrict__ ow0, const float* __restrict__ ow1)
{
    const float* src;
    float* dst;
    int n;
    switch (blockIdx.y) {
        case 0: src = x0;   dst = g_xtf;                       n = T0 * WIDTH; break;
        case 1: src = x1;   dst = g_xtf + T0 * WIDTH;          n = (TT - T0) * WIDTH; break;
        case 2: src = qgw0; dst = g_qgwtf;                     n = NH * WIDTH * 256; break;
        case 3: src = qgw1; dst = g_qgwtf + NH * WIDTH * 256;  n = NH * WIDTH * 256; break;
        case 4: src = kw0;  dst = g_kwtf;                      n = KH * WIDTH * HD; break;
        case 5: src = kw1;  dst = g_kwtf + KH * WIDTH * HD;    n = KH * WIDTH * HD; break;
        case 6: src = vw0;  dst = g_vwtf;                      n = KH * WIDTH * HD; break;
        case 7: src = vw1;  dst = g_vwtf + KH * WIDTH * HD;    n = KH * WIDTH * HD; break;
        case 8: src = ow0;  dst = g_owtf;                      n = NH * HD * WIDTH; break;
        default: src = ow1; dst = g_owtf + NH * HD * WIDTH;    n = NH * HD * WIDTH; break;
    }
    const int n4 = n >> 2;
    for (int i = blockIdx.x * 256 + threadIdx.x; i < n4; i += gridDim.x * 256) {
        float4 v = ((const float4*)src)[i];
        float4 o;
        o.x = __uint_as_float(f2tf(v.x));
        o.y = __uint_as_float(f2tf(v.y));
        o.z = __uint_as_float(f2tf(v.z));
        o.w = __uint_as_float(f2tf(v.w));
        ((float4*)dst)[i] = o;
    }
}

// ---------------------------------------------------------------------------
// cp.async pipelined tf32 GEMM core: inputs already tf32-rounded, no cvt.
// Optional second (tf32-rounded) output C2.
// ---------------------------------------------------------------------------
#define ASTRF 20
#define BSTRF 136
#define A_STAGE (128 * ASTRF)
#define B_STAGE (16 * BSTRF)
#define STAGE_F (A_STAGE + B_STAGE)
#define GEMM_SMEM_BYTES (3 * STAGE_F * 4)

__device__ __forceinline__ void issue_stage(
    uint32_t sbase, int stage, const float* A, int lda,
    const float* B, int ldb, int k0, int tid)
{
    const uint32_t aS = sbase + stage * (STAGE_F * 4);
    const uint32_t bS = aS + A_STAGE * 4;
    const int ar = tid >> 2, ak = (tid & 3) * 4;
    const int br = tid >> 5, bc = (tid & 31) * 4;
    cpasync16cg(aS + (ar * ASTRF + ak) * 4,          A + (long)ar * lda + k0 + ak);
    cpasync16cg(aS + ((64 + ar) * ASTRF + ak) * 4,   A + (long)(64 + ar) * lda + k0 + ak);
    cpasync16cg(bS + (br * BSTRF + bc) * 4,          B + (long)(k0 + br) * ldb + bc);
    cpasync16cg(bS + ((8 + br) * BSTRF + bc) * 4,    B + (long)(k0 + 8 + br) * ldb + bc);
    asm volatile("cp.async.commit_group;" ::: "memory");
}

__device__ void gemm_async_core(
    const float* __restrict__ A, int lda,
    const float* __restrict__ B, int ldb,
    float* __restrict__ C, float* __restrict__ C2, int ldc, int Kdim)
{
    extern __shared__ float smf[];
    const uint32_t sbase = smem_u32(smf);

    const int tid = threadIdx.x;
    const int lane = tid & 31;
    const int g = lane >> 2;
    const int t = lane & 3;
    const int wid = tid >> 5;
    const int mw = (wid >> 1) * 32;
    const int nw = (wid & 1) * 64;

    const int nt = Kdim / 16;

    issue_stage(sbase, 0, A, lda, B, ldb, 0, tid);
    issue_stage(sbase, 1, A, lda, B, ldb, 16, tid);

    float acc[2][8][4] = {};

    for (int kt = 0; kt < nt; kt++) {
        if (kt + 2 < nt) {
            issue_stage(sbase, (kt + 2) % 3, A, lda, B, ldb, (kt + 2) * 16, tid);
            asm volatile("cp.async.wait_group %0;" :: "n"(2) : "memory");
        } else if (kt + 1 < nt) {
            asm volatile("cp.async.wait_group %0;" :: "n"(1) : "memory");
        } else {
            asm volatile("cp.async.wait_group %0;" :: "n"(0) : "memory");
        }
        __syncthreads();

        const uint32_t* AsU = (const uint32_t*)(smf + (kt % 3) * STAGE_F);
        const uint32_t* BsU = AsU + A_STAGE;

        #pragma unroll
        for (int h = 0; h < 2; h++) {
            const int k0 = h * 8;
            uint32_t afr[2][4], bfr[8][2];
            #pragma unroll
            for (int tm = 0; tm < 2; tm++) {
                const int mb = mw + tm * 16;
                afr[tm][0] = AsU[(mb + g)     * ASTRF + k0 + t];
                afr[tm][1] = AsU[(mb + g + 8) * ASTRF + k0 + t];
                afr[tm][2] = AsU[(mb + g)     * ASTRF + k0 + t + 4];
                afr[tm][3] = AsU[(mb + g + 8) * ASTRF + k0 + t + 4];
            }
            #pragma unroll
            for (int tn = 0; tn < 8; tn++) {
                const int nb = nw + tn * 8 + g;
                bfr[tn][0] = BsU[(k0 + t)     * BSTRF + nb];
                bfr[tn][1] = BsU[(k0 + t + 4) * BSTRF + nb];
            }
            #pragma unroll
            for (int tm = 0; tm < 2; tm++)
                #pragma unroll
                for (int tn = 0; tn < 8; tn++)
                    mma8(acc[tm][tn], afr[tm], bfr[tn]);
        }
        __syncthreads();
    }

    #pragma unroll
    for (int tm = 0; tm < 2; tm++) {
        #pragma unroll
        for (int tn = 0; tn < 8; tn++) {
            const int r0 = mw + tm * 16 + g;
            const int cc = nw + tn * 8 + 2 * t;
            *(float2*)&C[r0 * ldc + cc]       = make_float2(acc[tm][tn][0], acc[tm][tn][1]);
            *(float2*)&C[(r0 + 8) * ldc + cc] = make_float2(acc[tm][tn][2], acc[tm][tn][3]);
            if (C2) {
                *(float2*)&C2[r0 * ldc + cc] = make_float2(
                    __uint_as_float(f2tf(acc[tm][tn][0])), __uint_as_float(f2tf(acc[tm][tn][1])));
                *(float2*)&C2[(r0 + 8) * ldc + cc] = make_float2(
                    __uint_as_float(f2tf(acc[tm][tn][2])), __uint_as_float(f2tf(acc[tm][tn][3])));
            }
        }
    }
}

// Fused projections: qg (y 0..31), K (y 32..35), V (y 36..39). grid (16, 40).
__global__ __launch_bounds__(256, 2) void proj_fused_kernel(
    float* __restrict__ qg, float* __restrict__ kraw,
    float* __restrict__ vcache, float* __restrict__ vtf)
{
    const int tile = blockIdx.x;
    const int y = blockIdx.y;
    const float* A = g_xtf + (long)tile * 128 * WIDTH;   // x0|x1 contiguous
    const float* B;
    float* C;
    float* C2 = nullptr;
    int ldb, ldc;
    if (y < 32) {
        const int n = y >> 1, bn = (y & 1) * 128;
        B = g_qgwtf + ((tile < 4) ? 0 : (long)NH * WIDTH * 256)
            + (long)n * WIDTH * 256 + bn;
        ldb = 256;
        C = qg + (long)tile * 128 * (NH * 256) + n * 256 + bn;
        ldc = NH * 256;
    } else if (y < 36) {
        const int kk = y - 32;
        B = g_kwtf + ((tile < 4) ? 0 : (long)KH * WIDTH * HD) + (long)kk * WIDTH * HD;
        ldb = HD;
        C = kraw + (long)tile * 128 * (KH * HD) + kk * HD;
        ldc = KH * HD;
    } else {
        const int kk = y - 36;
        B = g_vwtf + ((tile < 4) ? 0 : (long)KH * WIDTH * HD) + (long)kk * WIDTH * HD;
        ldb = HD;
        C = vcache + (long)tile * 128 * (KH * HD) + kk * HD;
        C2 = vtf + (long)tile * 128 * (KH * HD) + kk * HD;
        ldc = KH * HD;
    }
    gemm_async_core(A, WIDTH, B, ldb, C, C2, ldc, WIDTH);
}

// output projection: grid (16, 16). A = enc (already tf32-rounded by attn).
__global__ __launch_bounds__(256, 2) void proj_out_kernel(
    const float* __restrict__ enc, float* __restrict__ out)
{
    const int tile = blockIdx.x;
    const int bn = blockIdx.y * 128;
    const float* A = enc + (long)tile * 128 * (NH * HD);
    const float* B = g_owtf + ((tile < 4) ? 0 : (long)NH * HD * WIDTH) + bn;
    float* C = out + (long)tile * 128 * WIDTH + bn;
    gemm_async_core(A, NH * HD, B, WIDTH, C, nullptr, WIDTH, NH * HD);
}

// ---------------------------------------------------------------------------
// RMSNorm + RoPE
// ---------------------------------------------------------------------------
__global__ __launch_bounds__(128) void qnorm_rope(
    const float* __restrict__ qg, float* __restrict__ qout,
    const int* __restrict__ positions,
    const float* __restrict__ qn0, const float* __restrict__ qn1)
{
    int row  = blockIdx.x * 4 + (threadIdx.x >> 5);
    int lane = threadIdx.x & 31;
    int t = row >> 4;
    int n = row & 15;
    const float* src = qg + t * (NH * 256) + n * 256;

    float v0 = src[lane];
    float v1 = src[lane + 32];
    float v2 = src[lane + 64];
    float v3 = src[lane + 96];
    float ss = v0 * v0 + v1 * v1 + v2 * v2 + v3 * v3;
    #pragma unroll
    for (int o = 16; o; o >>= 1) ss += __shfl_xor_sync(0xffffffffu, ss, o);
    float inv = rsqrtf(ss * (1.0f / 128.0f) + 1e-6f);

    const float* qn = (t < T0) ? qn0 : qn1;
    v0 = v0 * inv * (1.0f + qn[lane]);
    v1 = v1 * inv * (1.0f + qn[lane + 32]);
    v2 = v2 * inv * (1.0f + qn[lane + 64]);
    v3 = v3 * inv * (1.0f + qn[lane + 96]);

    float p = (float)positions[t];
    float freq = powf(1000000.0f, -(float)lane / 32.0f);
    float s, c;
    sincosf(p * freq, &s, &c);

    const float SCL = 0.08838834764831845f;
    float* dst = qout + t * (NH * HD) + n * HD;
    dst[lane]      = __uint_as_float(f2tf((v0 * c - v1 * s) * SCL));
    dst[lane + 32] = __uint_as_float(f2tf((v1 * c + v0 * s) * SCL));
    dst[lane + 64] = __uint_as_float(f2tf(v2 * SCL));
    dst[lane + 96] = __uint_as_float(f2tf(v3 * SCL));
}

__global__ __launch_bounds__(128) void knorm_rope(
    const float* __restrict__ kraw, float* __restrict__ kcache,
    float* __restrict__ ktf,
    const int* __restrict__ positions,
    const float* __restrict__ kn0, const float* __restrict__ kn1)
{
    int row  = blockIdx.x * 4 + (threadIdx.x >> 5);
    int lane = threadIdx.x & 31;
    int t  = row >> 2;
    int kk = row & 3;
    const float* src = kraw + t * (KH * HD) + kk * HD;

    float v0 = src[lane];
    float v1 = src[lane + 32];
    float v2 = src[lane + 64];
    float v3 = src[lane + 96];
    float ss = v0 * v0 + v1 * v1 + v2 * v2 + v3 * v3;
    #pragma unroll
    for (int o = 16; o; o >>= 1) ss += __shfl_xor_sync(0xffffffffu, ss, o);
    float inv = rsqrtf(ss * (1.0f / 128.0f) + 1e-6f);

    const float* kn = (t < T0) ? kn0 : kn1;
    v0 = v0 * inv * (1.0f + kn[lane]);
    v1 = v1 * inv * (1.0f + kn[lane + 32]);
    v2 = v2 * inv * (1.0f + kn[lane + 64]);
    v3 = v3 * inv * (1.0f + kn[lane + 96]);

    float p = (float)positions[t];
    float freq = powf(1000000.0f, -(float)lane / 32.0f);
    float s, c;
    sincosf(p * freq, &s, &c);

    float r0 = v0 * c - v1 * s;
    float r1 = v1 * c + v0 * s;

    float* dst = kcache + t * (KH * HD) + kk * HD;
    dst[lane]      = r0;
    dst[lane + 32] = r1;
    dst[lane + 64] = v2;
    dst[lane + 96] = v3;

    float* dtf = ktf + t * (KH * HD) + kk * HD;
    dtf[lane]      = __uint_as_float(f2tf(r0));
    dtf[lane + 32] = __uint_as_float(f2tf(r1));
    dtf[lane + 64] = __uint_as_float(f2tf(v2));
    dtf[lane + 96] = __uint_as_float(f2tf(v3));
}

// ---------------------------------------------------------------------------
// Flash attention: 1 head x 64 queries per CTA, 128 threads (4 warps),
// 2 CTAs/SM. Q in REGISTERS. XOR-swizzled unpadded K/V slots (3-slot
// rotation) + warp-private swizzled P. FA2 register softmax, 3 barriers/iter.
// Writes enc pre-rounded to tf32 (consumed by proj_out without cvt).
// ---------------------------------------------------------------------------
#define SLOT_F (64 * 128)
#define AP_OFF (3 * SLOT_F)
#define ATT_SMEM_F (AP_OFF + 4 * 16 * 64)   // 112 KB

#define SWG(r, c16) ((r) * 32 + ((c16) ^ ((r) & 7)))
#define SWP(r, gq) ((r) * 16 + ((gq) ^ ((r) & 7)))

__device__ __forceinline__ void att_issue(
    uint32_t kvbase, int slot, const float* __restrict__ src, int sb, int tid)
{
    const uint32_t dst = kvbase + slot * (SLOT_F * 4);
    #pragma unroll
    for (int i = 0; i < 16; i++) {
        const int lin = tid + 128 * i;
        const int r = lin >> 5;
        const int c16 = lin & 31;
        cpasync16(dst + SWG(r, c16) * 16, src + (long)(sb + r) * (KH * HD) + c16 * 4);
    }
    asm volatile("cp.async.commit_group;" ::: "memory");
}

__global__ __launch_bounds__(128, 2) void attn_kernel(
    const float* __restrict__ q, const float* __restrict__ ktf,
    const float* __restrict__ vtf, const float* __restrict__ qg,
    float* __restrict__ enc)
{
    extern __shared__ float smf[];
    const uint32_t kvbase = smem_u32(smf);

    const int tid = threadIdx.x;
    const int lane = tid & 31;
    const int g = lane >> 2;
    const int t = lane & 3;
    const int wid = tid >> 5;
    const int mW = wid * 16;
    const int qt = gridDim.x - 1 - blockIdx.x;
    const int n = blockIdx.y;
    const int kvh = n >> 2;
    const int qbase = qt * 64;

    uint32_t* Pw = (uint32_t*)(smf + AP_OFF) + wid * (16 * 64);

    const float* kbase = ktf + kvh * HD;
    const float* vbase = vtf + kvh * HD;

    // stage Q into slot 2, then pull fragments into registers
    {
        const uint32_t qdst = kvbase + 2 * (SLOT_F * 4);
        #pragma unroll
        for (int i = 0; i < 16; i++) {
            const int lin = tid + 128 * i;
            const int r = lin >> 5;
            const int c16 = lin & 31;
            cpasync16(qdst + SWG(r, c16) * 16,
                      q + (long)(qbase + r) * (NH * HD) + n * HD + c16 * 4);
        }
        asm volatile("cp.async.commit_group;" ::: "memory");
        asm volatile("cp.async.wait_group 0;" ::: "memory");
        __syncthreads();
    }
    uint32_t qreg[16][4];
    {
        const uint32_t* Qs = (const uint32_t*)(smf + 2 * SLOT_F);
        #pragma unroll
        for (int ks = 0; ks < 16; ks++) {
            qreg[ks][0] = Qs[SWG(mW + g,     2 * ks) * 4 + t];
            qreg[ks][1] = Qs[SWG(mW + g + 8, 2 * ks) * 4 + t];
            qreg[ks][2] = Qs[SWG(mW + g,     2 * ks + 1) * 4 + t];
            qreg[ks][3] = Qs[SWG(mW + g + 8, 2 * ks + 1) * 4 + t];
        }
    }
    __syncthreads();

    att_issue(kvbase, 0, kbase, 0, tid);
    att_issue(kvbase, 1, vbase, 0, tid);

    float m0 = -3.0e38f, m1 = -3.0e38f, l0 = 0.0f, l1 = 0.0f;
    float accO[16][4] = {};

    for (int j = 0; j <= qt; j++) {
        const int nsb = (j + 1 <= qt) ? (j + 1) * 64 : qt * 64;

        asm volatile("cp.async.wait_group %0;" :: "n"(1) : "memory");
        __syncthreads();

        att_issue(kvbase, (2 * j + 2) % 3, kbase, nsb, tid);

        const uint32_t* Kf = (const uint32_t*)(smf + ((2 * j) % 3) * SLOT_F);
        float sacc[8][4] = {};
        #pragma unroll
        for (int ks = 0; ks < 16; ks++) {
            uint32_t bfr[8][2];
            #pragma unroll
            for (int tn = 0; tn < 8; tn++) {
                const int key = tn * 8 + g;
                bfr[tn][0] = Kf[SWG(key, 2 * ks) * 4 + t];
                bfr[tn][1] = Kf[SWG(key, 2 * ks + 1) * 4 + t];
            }
            #pragma unroll
            for (int tn = 0; tn < 8; tn++) mma8(sacc[tn], qreg[ks], bfr[tn]);
        }
        __syncthreads();

        att_issue(kvbase, (2 * j) % 3, vbase, nsb, tid);

        const int q0 = mW + g, q1 = mW + g + 8;
        if (j == qt) {
            #pragma unroll
            for (int tn = 0; tn < 8; tn++) {
                const int cc = tn * 8 + 2 * t;
                if (cc     > q0) sacc[tn][0] = NEGV;
                if (cc + 1 > q0) sacc[tn][1] = NEGV;
                if (cc     > q1) sacc[tn][2] = NEGV;
                if (cc + 1 > q1) sacc[tn][3] = NEGV;
            }
        }
        float rmax0 = -3.0e38f, rmax1 = -3.0e38f;
        #pragma unroll
        for (int tn = 0; tn < 8; tn++) {
            rmax0 = fmaxf(rmax0, fmaxf(sacc[tn][0], sacc[tn][1]));
            rmax1 = fmaxf(rmax1, fmaxf(sacc[tn][2], sacc[tn][3]));
        }
        rmax0 = fmaxf(rmax0, __shfl_xor_sync(0xffffffffu, rmax0, 1));
        rmax0 = fmaxf(rmax0, __shfl_xor_sync(0xffffffffu, rmax0, 2));
        rmax1 = fmaxf(rmax1, __shfl_xor_sync(0xffffffffu, rmax1, 1));
        rmax1 = fmaxf(rmax1, __shfl_xor_sync(0xffffffffu, rmax1, 2));
        const float mn0 = fmaxf(m0, rmax0);
        const float mn1 = fmaxf(m1, rmax1);
        const float al0 = __expf(m0 - mn0);
        const float al1 = __expf(m1 - mn1);
        m0 = mn0; m1 = mn1;

        float sum0 = 0.0f, sum1 = 0.0f;
        #pragma unroll
        for (int tn = 0; tn < 8; tn++) {
            float p0, p1, p2, p3;
            if (tn & 1) {
                p0 = exp_poly(sacc[tn][0] - mn0); p1 = exp_poly(sacc[tn][1] - mn0);
                p2 = exp_poly(sacc[tn][2] - mn1); p3 = exp_poly(sacc[tn][3] - mn1);
            } else {
                p0 = __expf(sacc[tn][0] - mn0); p1 = __expf(sacc[tn][1] - mn0);
                p2 = __expf(sacc[tn][2] - mn1); p3 = __expf(sacc[tn][3] - mn1);
            }
            sum0 += p0 + p1;
            sum1 += p2 + p3;
            const int pg = 2 * tn + (t >> 1);
            const int pw = (2 * t) & 3;
            const int i0 = SWP(g, pg) * 4 + pw;
            const int i1 = SWP(g + 8, pg) * 4 + pw;
            Pw[i0]     = f2tf(p0);
            Pw[i0 + 1] = f2tf(p1);
            Pw[i1]     = f2tf(p2);
            Pw[i1 + 1] = f2tf(p3);
        }
        sum0 += __shfl_xor_sync(0xffffffffu, sum0, 1);
        sum0 += __shfl_xor_sync(0xffffffffu, sum0, 2);
        sum1 += __shfl_xor_sync(0xffffffffu, sum1, 1);
        sum1 += __shfl_xor_sync(0xffffffffu, sum1, 2);
        l0 = l0 * al0 + sum0;
        l1 = l1 * al1 + sum1;

        #pragma unroll
        for (int tn = 0; tn < 16; tn++) {
            accO[tn][0] *= al0; accO[tn][1] *= al0;
            accO[tn][2] *= al1; accO[tn][3] *= al1;
        }

        asm volatile("cp.async.wait_group %0;" :: "n"(2) : "memory");
        __syncthreads();

        const uint32_t* Vf = (const uint32_t*)(smf + ((2 * j + 1) % 3) * SLOT_F);
        #pragma unroll
        for (int ks = 0; ks < 8; ks++) {
            uint32_t afr[4], bfr[16][2];
            afr[0] = Pw[SWP(g,     2 * ks) * 4 + t];
            afr[1] = Pw[SWP(g + 8, 2 * ks) * 4 + t];
            afr[2] = Pw[SWP(g,     2 * ks + 1) * 4 + t];
            afr[3] = Pw[SWP(g + 8, 2 * ks + 1) * 4 + t];
            const int k0 = ks * 8;
            #pragma unroll
            for (int tn = 0; tn < 16; tn++) {
                const int vg = 2 * tn + (g >> 2);
                const int vw = g & 3;
                bfr[tn][0] = Vf[SWG(k0 + t,     vg) * 4 + vw];
                bfr[tn][1] = Vf[SWG(k0 + t + 4, vg) * 4 + vw];
            }
            #pragma unroll
            for (int tn = 0; tn < 16; tn++) mma8(accO[tn], afr, bfr[tn]);
        }
    }

    asm volatile("cp.async.wait_group %0;" :: "n"(0) : "memory");

    // epilogue: 1/l scaling + fused sigmoid gate; store tf32-rounded enc
    const int qr0 = qbase + mW + g;
    const int qr1 = qr0 + 8;
    const float inv0 = 1.0f / l0;
    const float inv1 = 1.0f / l1;
    #pragma unroll
    for (int tn = 0; tn < 16; tn++) {
        const int cc = tn * 8 + 2 * t;
        float2 gg0 = *(const float2*)&qg[qr0 * (NH * 256) + n * 256 + 128 + cc];
        float2 gg1 = *(const float2*)&qg[qr1 * (NH * 256) + n * 256 + 128 + cc];
        float e00, e01, e10, e11;
        if (tn & 1) {
            e00 = exp_poly(-gg0.x); e01 = exp_poly(-gg0.y);
            e10 = exp_poly(-gg1.x); e11 = exp_poly(-gg1.y);
        } else {
            e00 = __expf(-gg0.x); e01 = __expf(-gg0.y);
            e10 = __expf(-gg1.x); e11 = __expf(-gg1.y);
        }
        float s00 = 1.0f / (1.0f + e00);
        float s01 = 1.0f / (1.0f + e01);
        float s10 = 1.0f / (1.0f + e10);
        float s11 = 1.0f / (1.0f + e11);
        float* d0 = enc + qr0 * (NH * HD) + n * HD + cc;
        float* d1 = enc + qr1 * (NH * HD) + n * HD + cc;
        *(float2*)d0 = make_float2(
            __uint_as_float(f2tf(accO[tn][0] * inv0 * s00)),
            __uint_as_float(f2tf(accO[tn][1] * inv0 * s01)));
        *(float2*)d1 = make_float2(
            __uint_as_float(f2tf(accO[tn][2] * inv1 * s10)),
            __uint_as_float(f2tf(accO[tn][3] * inv1 * s11)));
    }
}

// ---------------------------------------------------------------------------
extern "C" void kernel_launch(void* const* d_in, const int* in_sizes, int n_in,
                              void* d_out, int out_size)
{
    const float* x0    = (const float*)d_in[0];
    const float* x1    = (const float*)d_in[1];
    const int*   pos   = (const int*)d_in[2];
    const float* qg_w0 = (const float*)d_in[4];
    const float* k_w0  = (const float*)d_in[5];
    const float* v_w0  = (const float*)d_in[6];
    const float* qn0   = (const float*)d_in[7];
    const float* kn0   = (const float*)d_in[8];
    const float* o_w0  = (const float*)d_in[9];
    const float* qg_w1 = (const float*)d_in[10];
    const float* k_w1  = (const float*)d_in[11];
    const float* v_w1  = (const float*)d_in[12];
    const float* qn1   = (const float*)d_in[13];
    const float* kn1   = (const float*)d_in[14];
    const float* o_w1  = (const float*)d_in[15];

    float* out = (float*)d_out;

    float *qg, *kraw, *q, *enc, *ktf, *vtf;
    cudaGetSymbolAddress((void**)&qg,   g_qg);
    cudaGetSymbolAddress((void**)&kraw, g_kraw);
    cudaGetSymbolAddress((void**)&q,    g_q);
    cudaGetSymbolAddress((void**)&enc,  g_enc);
    cudaGetSymbolAddress((void**)&ktf,  g_ktf);
    cudaGetSymbolAddress((void**)&vtf,  g_vtf);

    cudaFuncSetAttribute(proj_fused_kernel, cudaFuncAttributeMaxDynamicSharedMemorySize, GEMM_SMEM_BYTES);
    cudaFuncSetAttribute(proj_out_kernel,   cudaFuncAttributeMaxDynamicSharedMemorySize, GEMM_SMEM_BYTES);
    cudaFuncSetAttribute(attn_kernel, cudaFuncAttributeMaxDynamicSharedMemorySize,
                         ATT_SMEM_F * sizeof(float));

    // pre-round all GEMM operands to tf32
    preround_kernel<<<dim3(512, 10), 256>>>(x0, x1, qg_w0, qg_w1,
                                            k_w0, k_w1, v_w0, v_w1, o_w0, o_w1);

    // all projections in one launch (V dual-written: exact -> d_out, tf32 -> scratch)
    proj_fused_kernel<<<dim3(16, 40), 256, GEMM_SMEM_BYTES>>>(
        qg, kraw, out + VC_BASE, vtf);

    // norms + rope (K dual-written; Q pre-rounded to tf32)
    qnorm_rope<<<TT*NH/4, 128>>>(qg, q, pos, qn0, qn1);
    knorm_rope<<<TT*KH/4, 128>>>(kraw, out + KC_BASE, ktf, pos, kn0, kn1);

    // attention: 1 head per CTA, Q in regs, 2 CTAs/SM, fused gate, tf32 enc out
    attn_kernel<<<dim3(TT/64, NH), 128, ATT_SMEM_F * sizeof(float)>>>(
        q, ktf, vtf, qg, enc);

    // output projection (no cvt: enc and o_w pre-rounded)
    proj_out_kernel<<<dim3(16, 16), 256, GEMM_SMEM_BYTES>>>(enc, out);
}